// round 14
// baseline (speedup 1.0000x reference)
#include <cuda_runtime.h>
#include <cstdint>

#define N_NODES 50000
#define E_EDGES 1600000
#define IN_DIM  128
#define OUT_DIM 64
#define SLOPE   0.1f
#define EPS     1e-12f

// Scratch (static __device__ arrays — no allocation anywhere)
__device__ float g_new[(size_t)N_NODES * OUT_DIM];   // projected features (12.8 MB)
__device__ float g_ssrc[N_NODES];                     // new[i] . a_src
__device__ float g_sdst[N_NODES];                     // new[i] . a_dst
__device__ int   g_cnt[N_NODES];                      // per-src edge counts
__device__ int   g_off[N_NODES];                      // exclusive offsets (CSR)
__device__ int   g_pos[N_NODES];                      // running fill cursor
__device__ int2  g_edge[E_EDGES];                     // (dst, bits(w)) binned by src
__device__ int   g_idx32;                             // 1 if edge_index is int32
__device__ int   g_blk[64];                           // per-block scan partials

// ---- packed f32x2 helpers (Blackwell; FFMA2 only reachable via PTX) --------
__device__ __forceinline__ void fma2(unsigned long long& acc,
                                     unsigned long long a, unsigned long long b)
{
    asm("fma.rn.f32x2 %0, %1, %2, %0;" : "+l"(acc) : "l"(a), "l"(b));
}
__device__ __forceinline__ unsigned long long pack2(float lo, float hi)
{
    unsigned long long r;
    asm("mov.b64 %0, {%1, %2};" : "=l"(r) : "f"(lo), "f"(hi));
    return r;
}
__device__ __forceinline__ float2 unpack2(unsigned long long v)
{
    float2 r;
    asm("mov.b64 {%0, %1}, %2;" : "=f"(r.x), "=f"(r.y) : "l"(v));
    return r;
}

// ---------------------------------------------------------------------------
// Kernel 0: zero g_cnt + dtype probe (sampled odd words of first 8192 slots).
// ---------------------------------------------------------------------------
__global__ void probe_zero_kernel(const unsigned* __restrict__ w)
{
    int i = blockIdx.x * blockDim.x + threadIdx.x;
    if (i < N_NODES) g_cnt[i] = 0;
    if (i < 8192 && w[2 * i + 1]) g_idx32 = 1;   // monotonic, deterministic
}

// ---------------------------------------------------------------------------
// Kernel 1: new = x @ W^T + b ; fused s_src/s_dst dots; fused src histogram.
// ---------------------------------------------------------------------------
#define GEMM_ROWS 32
__global__ __launch_bounds__(128)
void gemm_attn_hist_kernel(const float* __restrict__ x,
                           const float* __restrict__ W,
                           const float* __restrict__ b,
                           const float* __restrict__ a,
                           const void* __restrict__ ei)
{
    __shared__ float Wt[IN_DIM * OUT_DIM];          // 32 KB  [k][col]
    __shared__ float xs[GEMM_ROWS * IN_DIM];        // 16 KB

    const int tid  = threadIdx.x;
    const int row0 = blockIdx.x * GEMM_ROWS;

    // Load W (64x128) transposed into Wt
    {
        const float4* W4 = reinterpret_cast<const float4*>(W);
        for (int i = tid; i < (OUT_DIM * IN_DIM) / 4; i += 128) {
            int r  = i >> 5;            // output col (W row) 0..63
            int k4 = (i & 31) * 4;      // k
            float4 v = W4[i];
            Wt[(k4 + 0) * OUT_DIM + r] = v.x;
            Wt[(k4 + 1) * OUT_DIM + r] = v.y;
            Wt[(k4 + 2) * OUT_DIM + r] = v.z;
            Wt[(k4 + 3) * OUT_DIM + r] = v.w;
        }
    }
    // Load 32 x-rows
    {
        const float4* x4 = reinterpret_cast<const float4*>(x);
        float4* xs4 = reinterpret_cast<float4*>(xs);
        for (int i = tid; i < (GEMM_ROWS * IN_DIM) / 4; i += 128) {
            int row = row0 + (i >> 5);
            if (row < N_NODES) xs4[i] = x4[(size_t)row * 32 + (i & 31)];
        }
    }
    __syncthreads();

    const int c4 = tid & 15;        // col group (4*c4 .. 4*c4+3)
    const int rp = tid >> 4;        // 0..7 -> rows 4*rp .. 4*rp+3 (local)
    const int c  = 4 * c4;

    unsigned long long alo[4] = {0, 0, 0, 0};   // cols c, c+1
    unsigned long long ahi[4] = {0, 0, 0, 0};   // cols c+2, c+3
    const float* xr0 = xs + (rp * 4 + 0) * IN_DIM;
    const float* xr1 = xs + (rp * 4 + 1) * IN_DIM;
    const float* xr2 = xs + (rp * 4 + 2) * IN_DIM;
    const float* xr3 = xs + (rp * 4 + 3) * IN_DIM;

    #pragma unroll 8
    for (int k = 0; k < IN_DIM; k++) {
        ulonglong2 wv = *reinterpret_cast<const ulonglong2*>(Wt + k * OUT_DIM + c);
        unsigned long long x0 = pack2(xr0[k], xr0[k]);
        unsigned long long x1 = pack2(xr1[k], xr1[k]);
        unsigned long long x2 = pack2(xr2[k], xr2[k]);
        unsigned long long x3 = pack2(xr3[k], xr3[k]);
        fma2(alo[0], x0, wv.x); fma2(ahi[0], x0, wv.y);
        fma2(alo[1], x1, wv.x); fma2(ahi[1], x1, wv.y);
        fma2(alo[2], x2, wv.x); fma2(ahi[2], x2, wv.y);
        fma2(alo[3], x3, wv.x); fma2(ahi[3], x3, wv.y);
    }

    float4 b4  = reinterpret_cast<const float4*>(b)[c4];
    float4 as4 = reinterpret_cast<const float4*>(a)[c4];       // a_src slice
    float4 ad4 = reinterpret_cast<const float4*>(a)[16 + c4];  // a_dst slice

    float4* gn = reinterpret_cast<float4*>(g_new);
    float ps[4], pd[4];
    #pragma unroll
    for (int i = 0; i < 4; i++) {
        float2 lo = unpack2(alo[i]);
        float2 hi = unpack2(ahi[i]);
        float4 av = make_float4(lo.x + b4.x, lo.y + b4.y, hi.x + b4.z, hi.y + b4.w);
        int row = row0 + rp * 4 + i;
        if (row < N_NODES) gn[(size_t)row * 16 + c4] = av;
        ps[i] = av.x * as4.x + av.y * as4.y + av.z * as4.z + av.w * as4.w;
        pd[i] = av.x * ad4.x + av.y * ad4.y + av.z * ad4.z + av.w * ad4.w;
    }
    #pragma unroll
    for (int off = 8; off > 0; off >>= 1) {
        #pragma unroll
        for (int i = 0; i < 4; i++) {
            ps[i] += __shfl_down_sync(0xffffffffu, ps[i], off, 16);
            pd[i] += __shfl_down_sync(0xffffffffu, pd[i], off, 16);
        }
    }
    if (c4 == 0) {
        #pragma unroll
        for (int i = 0; i < 4; i++) {
            int row = row0 + rp * 4 + i;
            if (row < N_NODES) { g_ssrc[row] = ps[i]; g_sdst[row] = pd[i]; }
        }
    }

    // ---- fused histogram tail
    {
        const int nt = gridDim.x * 128;
        for (int t = blockIdx.x * 128 + tid; t < E_EDGES / 4; t += nt) {
            int4 s4;
            if (g_idx32) {
                s4 = reinterpret_cast<const int4*>(ei)[t];
            } else {
                longlong2 p0 = reinterpret_cast<const longlong2*>(ei)[2 * t];
                longlong2 p1 = reinterpret_cast<const longlong2*>(ei)[2 * t + 1];
                s4 = make_int4((int)p0.x, (int)p0.y, (int)p1.x, (int)p1.y);
            }
            atomicAdd(&g_cnt[s4.x], 1);
            atomicAdd(&g_cnt[s4.y], 1);
            atomicAdd(&g_cnt[s4.z], 1);
            atomicAdd(&g_cnt[s4.w], 1);
        }
    }
}

// ---------------------------------------------------------------------------
// Scan, 3-pass multi-block. 49 blocks x 256 threads x 4 items = 50176 >= N.
// ---------------------------------------------------------------------------
#define SCAN_BLOCKS 49
#define SCAN_THREADS 256
#define SCAN_ITEMS 4

__global__ __launch_bounds__(SCAN_THREADS)
void scan_part_kernel()
{
    __shared__ int wsum[8];
    const int t = threadIdx.x;
    const int base = (blockIdx.x * SCAN_THREADS + t) * SCAN_ITEMS;

    int s = 0;
    #pragma unroll
    for (int i = 0; i < SCAN_ITEMS; i++) {
        int idx = base + i;
        if (idx < N_NODES) s += g_cnt[idx];
    }
    #pragma unroll
    for (int off = 16; off > 0; off >>= 1) s += __shfl_down_sync(0xffffffffu, s, off);
    if ((t & 31) == 0) wsum[t >> 5] = s;
    __syncthreads();
    if (t == 0) {
        int tot = 0;
        #pragma unroll
        for (int i = 0; i < 8; i++) tot += wsum[i];
        g_blk[blockIdx.x] = tot;
    }
}

// Pass 2: warp-parallel exclusive scan of 49 block totals (one warp)
__global__ void scan_top_kernel()
{
    const int lane = threadIdx.x;
    int a0 = (lane < SCAN_BLOCKS) ? g_blk[lane] : 0;
    int a1 = (32 + lane < SCAN_BLOCKS) ? g_blk[32 + lane] : 0;

    // inclusive scan row 0
    int v0 = a0;
    #pragma unroll
    for (int off = 1; off < 32; off <<= 1) {
        int n = __shfl_up_sync(0xffffffffu, v0, off);
        if (lane >= off) v0 += n;
    }
    int tot0 = __shfl_sync(0xffffffffu, v0, 31);
    // inclusive scan row 1
    int v1 = a1;
    #pragma unroll
    for (int off = 1; off < 32; off <<= 1) {
        int n = __shfl_up_sync(0xffffffffu, v1, off);
        if (lane >= off) v1 += n;
    }
    if (lane < SCAN_BLOCKS) g_blk[lane] = v0 - a0;
    if (32 + lane < SCAN_BLOCKS) g_blk[32 + lane] = tot0 + v1 - a1;
}

__global__ __launch_bounds__(SCAN_THREADS)
void scan_write_kernel()
{
    __shared__ int wbase[8];
    const int t = threadIdx.x;
    const int lane = t & 31, wid = t >> 5;
    const int base = (blockIdx.x * SCAN_THREADS + t) * SCAN_ITEMS;

    int c[SCAN_ITEMS];
    int s = 0;
    #pragma unroll
    for (int i = 0; i < SCAN_ITEMS; i++) {
        int idx = base + i;
        c[i] = (idx < N_NODES) ? g_cnt[idx] : 0;
        s += c[i];
    }
    int v = s;
    #pragma unroll
    for (int off = 1; off < 32; off <<= 1) {
        int n = __shfl_up_sync(0xffffffffu, v, off);
        if (lane >= off) v += n;
    }
    if (lane == 31) wbase[wid] = v;
    __syncthreads();
    if (t == 0) {
        int run = 0;
        #pragma unroll
        for (int i = 0; i < 8; i++) { int w = wbase[i]; wbase[i] = run; run += w; }
    }
    __syncthreads();

    int run = g_blk[blockIdx.x] + wbase[wid] + (v - s);   // exclusive prefix
    #pragma unroll
    for (int i = 0; i < SCAN_ITEMS; i++) {
        int idx = base + i;
        if (idx < N_NODES) {
            g_off[idx] = run;
            g_pos[idx] = run;
            run += c[i];
        }
    }
}

// ---------------------------------------------------------------------------
// Kernel 4: bin edges into CSR, computing w per edge. 4 edges/thread.
// ---------------------------------------------------------------------------
__global__ __launch_bounds__(256)
void bin_kernel(const void* __restrict__ ei)
{
    int t = blockIdx.x * blockDim.x + threadIdx.x;
    if (t >= E_EDGES / 4) return;
    int4 s4, d4;
    if (g_idx32) {
        s4 = reinterpret_cast<const int4*>(ei)[t];
        d4 = reinterpret_cast<const int4*>(ei)[E_EDGES / 4 + t];
    } else {
        longlong2 p0 = reinterpret_cast<const longlong2*>(ei)[2 * t];
        longlong2 p1 = reinterpret_cast<const longlong2*>(ei)[2 * t + 1];
        longlong2 q0 = reinterpret_cast<const longlong2*>(ei)[E_EDGES / 2 + 2 * t];
        longlong2 q1 = reinterpret_cast<const longlong2*>(ei)[E_EDGES / 2 + 2 * t + 1];
        s4 = make_int4((int)p0.x, (int)p0.y, (int)p1.x, (int)p1.y);
        d4 = make_int4((int)q0.x, (int)q0.y, (int)q1.x, (int)q1.y);
    }
    int ss[4] = {s4.x, s4.y, s4.z, s4.w};
    int dd[4] = {d4.x, d4.y, d4.z, d4.w};
    #pragma unroll
    for (int i = 0; i < 4; i++) {
        float score = g_ssrc[ss[i]] + g_sdst[dd[i]];
        float lr = score > 0.f ? score : SLOPE * score;
        float w = __expf(lr);
        int pos = atomicAdd(&g_pos[ss[i]], 1);
        g_edge[pos] = make_int2(dd[i], __float_as_int(w));
    }
}

// ---------------------------------------------------------------------------
// Kernel 5: aggregate. TWO warps per node = 4 substreams of 16 lanes.
// Each substream strides 4 edges, 4-deep unroll (16 edges/iter/node).
// Cross-warp combine via smem. FFMA2 accumulate.
// ---------------------------------------------------------------------------
__global__ __launch_bounds__(256)
void aggregate_kernel(float* __restrict__ out)
{
    __shared__ float4 sacc[8][16];
    __shared__ float  srs[8];

    const int tid   = threadIdx.x;
    const int group = tid >> 6;              // 4 nodes per block
    const int gtid  = tid & 63;
    const int node  = blockIdx.x * 4 + group;
    const int sub   = gtid >> 4;             // substream 0..3
    const int sl    = gtid & 15;             // float4 slot within row
    const int wid   = tid >> 5;              // warp 0..7
    const int lane  = tid & 31;

    float4 accv = {0.f, 0.f, 0.f, 0.f};
    float rsum = 0.f;

    if (node < N_NODES) {
        const int beg = g_off[node];
        const int end = beg + g_cnt[node];

        unsigned long long axy = 0, azw = 0;
        const ulonglong2* gn = reinterpret_cast<const ulonglong2*>(g_new);

        int j = beg + sub;
        for (; j + 12 < end; j += 16) {
            int2 e0 = g_edge[j + 0];
            int2 e1 = g_edge[j + 4];
            int2 e2 = g_edge[j + 8];
            int2 e3 = g_edge[j + 12];
            ulonglong2 v0 = gn[(size_t)e0.x * 16 + sl];
            ulonglong2 v1 = gn[(size_t)e1.x * 16 + sl];
            ulonglong2 v2 = gn[(size_t)e2.x * 16 + sl];
            ulonglong2 v3 = gn[(size_t)e3.x * 16 + sl];
            float w0 = __int_as_float(e0.y), w1 = __int_as_float(e1.y);
            float w2 = __int_as_float(e2.y), w3 = __int_as_float(e3.y);
            unsigned long long wd0 = pack2(w0, w0), wd1 = pack2(w1, w1);
            unsigned long long wd2 = pack2(w2, w2), wd3 = pack2(w3, w3);
            fma2(axy, wd0, v0.x); fma2(azw, wd0, v0.y);
            fma2(axy, wd1, v1.x); fma2(azw, wd1, v1.y);
            fma2(axy, wd2, v2.x); fma2(azw, wd2, v2.y);
            fma2(axy, wd3, v3.x); fma2(azw, wd3, v3.y);
            rsum += (w0 + w1) + (w2 + w3);
        }
        for (; j < end; j += 4) {
            int2 e0 = g_edge[j];
            ulonglong2 v0 = gn[(size_t)e0.x * 16 + sl];
            float w0 = __int_as_float(e0.y);
            unsigned long long wd0 = pack2(w0, w0);
            fma2(axy, wd0, v0.x); fma2(azw, wd0, v0.y);
            rsum += w0;
        }

        float2 vxy = unpack2(axy);
        float2 vzw = unpack2(azw);
        accv = make_float4(vxy.x, vxy.y, vzw.x, vzw.y);
    }

    // intra-warp: combine the warp's two substreams (lanes l <-> l+16)
    accv.x += __shfl_xor_sync(0xffffffffu, accv.x, 16);
    accv.y += __shfl_xor_sync(0xffffffffu, accv.y, 16);
    accv.z += __shfl_xor_sync(0xffffffffu, accv.z, 16);
    accv.w += __shfl_xor_sync(0xffffffffu, accv.w, 16);
    rsum   += __shfl_xor_sync(0xffffffffu, rsum, 16);

    if (lane < 16) sacc[wid][lane] = accv;
    if (lane == 0) srs[wid] = rsum;
    __syncthreads();

    // cross-warp: first 16 lanes of the group's even warp finalize
    if (node < N_NODES && (gtid < 16)) {
        float4 p = sacc[group * 2 + 1][sl];
        float4 q = sacc[group * 2][sl];
        float rs = srs[group * 2] + srs[group * 2 + 1];
        float inv = 1.0f / (rs + EPS);
        reinterpret_cast<float4*>(out)[(size_t)node * 16 + sl] =
            make_float4((q.x + p.x) * inv, (q.y + p.y) * inv,
                        (q.z + p.z) * inv, (q.w + p.w) * inv);
    }
}

extern "C" void kernel_launch(void* const* d_in, const int* in_sizes, int n_in,
                              void* d_out, int out_size)
{
    // Size-based dispatch (all element counts distinct) — immune to ordering.
    const float* x = 0; const void* ei = 0; const float* W = 0;
    const float* b = 0; const float* a = 0;
    for (int i = 0; i < n_in; i++) {
        switch (in_sizes[i]) {
            case N_NODES * IN_DIM:       x  = (const float*)d_in[i]; break; // 6.4M
            case 2 * E_EDGES:            ei = d_in[i];               break; // 3.2M
            case OUT_DIM * IN_DIM:       W  = (const float*)d_in[i]; break; // 8192
            case OUT_DIM:                b  = (const float*)d_in[i]; break; // 64
            case 2 * OUT_DIM:            a  = (const float*)d_in[i]; break; // 128
        }
    }
    float* out = (float*)d_out;

    probe_zero_kernel<<<(N_NODES + 255) / 256, 256>>>((const unsigned*)ei);
    gemm_attn_hist_kernel<<<(N_NODES + GEMM_ROWS - 1) / GEMM_ROWS, 128>>>(x, W, b, a, ei);
    scan_part_kernel<<<SCAN_BLOCKS, SCAN_THREADS>>>();
    scan_top_kernel<<<1, 32>>>();
    scan_write_kernel<<<SCAN_BLOCKS, SCAN_THREADS>>>();
    bin_kernel<<<(E_EDGES / 4 + 255) / 256, 256>>>(ei);
    aggregate_kernel<<<(N_NODES / 4 + 1), 256>>>(out);
}

// round 15
// speedup vs baseline: 1.0975x; 1.0975x over previous
#include <cuda_runtime.h>
#include <cstdint>

#define N_NODES 50000
#define E_EDGES 1600000
#define IN_DIM  128
#define OUT_DIM 64
#define SLOPE   0.1f
#define EPS     1e-12f

// Scratch (static __device__ arrays — no allocation anywhere)
__device__ float g_new[(size_t)N_NODES * OUT_DIM];   // projected features (12.8 MB)
__device__ float g_ssrc[N_NODES];                     // new[i] . a_src
__device__ float g_sdst[N_NODES];                     // new[i] . a_dst
__device__ int   g_cnt[N_NODES];                      // per-src edge counts
__device__ int   g_off[N_NODES];                      // exclusive offsets (CSR)
__device__ int   g_pos[N_NODES];                      // running fill cursor
__device__ int2  g_edge[E_EDGES];                     // (dst, bits(w)) binned by src
__device__ int   g_idx32;                             // 1 if edge_index is int32
__device__ int   g_blk[64];                           // per-block scan partials

// ---- packed f32x2 helpers (Blackwell; FFMA2 only reachable via PTX) --------
__device__ __forceinline__ void fma2(unsigned long long& acc,
                                     unsigned long long a, unsigned long long b)
{
    asm("fma.rn.f32x2 %0, %1, %2, %0;" : "+l"(acc) : "l"(a), "l"(b));
}
__device__ __forceinline__ unsigned long long pack2(float lo, float hi)
{
    unsigned long long r;
    asm("mov.b64 %0, {%1, %2};" : "=l"(r) : "f"(lo), "f"(hi));
    return r;
}
__device__ __forceinline__ float2 unpack2(unsigned long long v)
{
    float2 r;
    asm("mov.b64 {%0, %1}, %2;" : "=f"(r.x), "=f"(r.y) : "l"(v));
    return r;
}

// ---------------------------------------------------------------------------
// Kernel 0: zero g_cnt + dtype probe (sampled odd words of first 8192 slots).
// ---------------------------------------------------------------------------
__global__ void probe_zero_kernel(const unsigned* __restrict__ w)
{
    int i = blockIdx.x * blockDim.x + threadIdx.x;
    if (i < N_NODES) g_cnt[i] = 0;
    if (i < 8192 && w[2 * i + 1]) g_idx32 = 1;   // monotonic, deterministic
}

// ---------------------------------------------------------------------------
// Kernel 1: new = x @ W^T + b ; fused s_src/s_dst dots; fused src histogram.
// ---------------------------------------------------------------------------
#define GEMM_ROWS 32
__global__ __launch_bounds__(128)
void gemm_attn_hist_kernel(const float* __restrict__ x,
                           const float* __restrict__ W,
                           const float* __restrict__ b,
                           const float* __restrict__ a,
                           const void* __restrict__ ei)
{
    __shared__ float Wt[IN_DIM * OUT_DIM];          // 32 KB  [k][col]
    __shared__ float xs[GEMM_ROWS * IN_DIM];        // 16 KB

    const int tid  = threadIdx.x;
    const int row0 = blockIdx.x * GEMM_ROWS;

    // Load W (64x128) transposed into Wt
    {
        const float4* W4 = reinterpret_cast<const float4*>(W);
        for (int i = tid; i < (OUT_DIM * IN_DIM) / 4; i += 128) {
            int r  = i >> 5;            // output col (W row) 0..63
            int k4 = (i & 31) * 4;      // k
            float4 v = W4[i];
            Wt[(k4 + 0) * OUT_DIM + r] = v.x;
            Wt[(k4 + 1) * OUT_DIM + r] = v.y;
            Wt[(k4 + 2) * OUT_DIM + r] = v.z;
            Wt[(k4 + 3) * OUT_DIM + r] = v.w;
        }
    }
    // Load 32 x-rows
    {
        const float4* x4 = reinterpret_cast<const float4*>(x);
        float4* xs4 = reinterpret_cast<float4*>(xs);
        for (int i = tid; i < (GEMM_ROWS * IN_DIM) / 4; i += 128) {
            int row = row0 + (i >> 5);
            if (row < N_NODES) xs4[i] = x4[(size_t)row * 32 + (i & 31)];
        }
    }
    __syncthreads();

    const int c4 = tid & 15;        // col group (4*c4 .. 4*c4+3)
    const int rp = tid >> 4;        // 0..7 -> rows 4*rp .. 4*rp+3 (local)
    const int c  = 4 * c4;

    unsigned long long alo[4] = {0, 0, 0, 0};   // cols c, c+1
    unsigned long long ahi[4] = {0, 0, 0, 0};   // cols c+2, c+3
    const float* xr0 = xs + (rp * 4 + 0) * IN_DIM;
    const float* xr1 = xs + (rp * 4 + 1) * IN_DIM;
    const float* xr2 = xs + (rp * 4 + 2) * IN_DIM;
    const float* xr3 = xs + (rp * 4 + 3) * IN_DIM;

    #pragma unroll 8
    for (int k = 0; k < IN_DIM; k++) {
        ulonglong2 wv = *reinterpret_cast<const ulonglong2*>(Wt + k * OUT_DIM + c);
        unsigned long long x0 = pack2(xr0[k], xr0[k]);
        unsigned long long x1 = pack2(xr1[k], xr1[k]);
        unsigned long long x2 = pack2(xr2[k], xr2[k]);
        unsigned long long x3 = pack2(xr3[k], xr3[k]);
        fma2(alo[0], x0, wv.x); fma2(ahi[0], x0, wv.y);
        fma2(alo[1], x1, wv.x); fma2(ahi[1], x1, wv.y);
        fma2(alo[2], x2, wv.x); fma2(ahi[2], x2, wv.y);
        fma2(alo[3], x3, wv.x); fma2(ahi[3], x3, wv.y);
    }

    float4 b4  = reinterpret_cast<const float4*>(b)[c4];
    float4 as4 = reinterpret_cast<const float4*>(a)[c4];       // a_src slice
    float4 ad4 = reinterpret_cast<const float4*>(a)[16 + c4];  // a_dst slice

    float4* gn = reinterpret_cast<float4*>(g_new);
    float ps[4], pd[4];
    #pragma unroll
    for (int i = 0; i < 4; i++) {
        float2 lo = unpack2(alo[i]);
        float2 hi = unpack2(ahi[i]);
        float4 av = make_float4(lo.x + b4.x, lo.y + b4.y, hi.x + b4.z, hi.y + b4.w);
        int row = row0 + rp * 4 + i;
        if (row < N_NODES) gn[(size_t)row * 16 + c4] = av;
        ps[i] = av.x * as4.x + av.y * as4.y + av.z * as4.z + av.w * as4.w;
        pd[i] = av.x * ad4.x + av.y * ad4.y + av.z * ad4.z + av.w * ad4.w;
    }
    #pragma unroll
    for (int off = 8; off > 0; off >>= 1) {
        #pragma unroll
        for (int i = 0; i < 4; i++) {
            ps[i] += __shfl_down_sync(0xffffffffu, ps[i], off, 16);
            pd[i] += __shfl_down_sync(0xffffffffu, pd[i], off, 16);
        }
    }
    if (c4 == 0) {
        #pragma unroll
        for (int i = 0; i < 4; i++) {
            int row = row0 + rp * 4 + i;
            if (row < N_NODES) { g_ssrc[row] = ps[i]; g_sdst[row] = pd[i]; }
        }
    }

    // ---- fused histogram tail
    {
        const int nt = gridDim.x * 128;
        for (int t = blockIdx.x * 128 + tid; t < E_EDGES / 4; t += nt) {
            int4 s4;
            if (g_idx32) {
                s4 = reinterpret_cast<const int4*>(ei)[t];
            } else {
                longlong2 p0 = reinterpret_cast<const longlong2*>(ei)[2 * t];
                longlong2 p1 = reinterpret_cast<const longlong2*>(ei)[2 * t + 1];
                s4 = make_int4((int)p0.x, (int)p0.y, (int)p1.x, (int)p1.y);
            }
            atomicAdd(&g_cnt[s4.x], 1);
            atomicAdd(&g_cnt[s4.y], 1);
            atomicAdd(&g_cnt[s4.z], 1);
            atomicAdd(&g_cnt[s4.w], 1);
        }
    }
}

// ---------------------------------------------------------------------------
// Scan, 2-pass multi-block. 49 blocks x 256 threads x 4 items = 50176 >= N.
// ---------------------------------------------------------------------------
#define SCAN_BLOCKS 49
#define SCAN_THREADS 256
#define SCAN_ITEMS 4

__global__ __launch_bounds__(SCAN_THREADS)
void scan_part_kernel()
{
    __shared__ int wsum[8];
    const int t = threadIdx.x;
    const int base = (blockIdx.x * SCAN_THREADS + t) * SCAN_ITEMS;

    int s = 0;
    #pragma unroll
    for (int i = 0; i < SCAN_ITEMS; i++) {
        int idx = base + i;
        if (idx < N_NODES) s += g_cnt[idx];
    }
    #pragma unroll
    for (int off = 16; off > 0; off >>= 1) s += __shfl_down_sync(0xffffffffu, s, off);
    if ((t & 31) == 0) wsum[t >> 5] = s;
    __syncthreads();
    if (t == 0) {
        int tot = 0;
        #pragma unroll
        for (int i = 0; i < 8; i++) tot += wsum[i];
        g_blk[blockIdx.x] = tot;
    }
}

// Pass 2: write exclusive offsets. Each block derives its own base by
// reducing g_blk[0..blockIdx.x) — removes the separate scan_top launch.
__global__ __launch_bounds__(SCAN_THREADS)
void scan_write_kernel()
{
    __shared__ int wbase[8];
    __shared__ int sbase;
    const int t = threadIdx.x;
    const int lane = t & 31, wid = t >> 5;
    const int base = (blockIdx.x * SCAN_THREADS + t) * SCAN_ITEMS;

    // warp 0: block base = sum of totals of preceding blocks
    if (wid == 0) {
        int v = 0;
        for (int i = lane; i < blockIdx.x; i += 32) v += g_blk[i];
        #pragma unroll
        for (int off = 16; off > 0; off >>= 1) v += __shfl_down_sync(0xffffffffu, v, off);
        if (lane == 0) sbase = v;
    }

    int c[SCAN_ITEMS];
    int s = 0;
    #pragma unroll
    for (int i = 0; i < SCAN_ITEMS; i++) {
        int idx = base + i;
        c[i] = (idx < N_NODES) ? g_cnt[idx] : 0;
        s += c[i];
    }
    int v = s;
    #pragma unroll
    for (int off = 1; off < 32; off <<= 1) {
        int n = __shfl_up_sync(0xffffffffu, v, off);
        if (lane >= off) v += n;
    }
    if (lane == 31) wbase[wid] = v;
    __syncthreads();
    if (t == 0) {
        int run = sbase;
        #pragma unroll
        for (int i = 0; i < 8; i++) { int w = wbase[i]; wbase[i] = run; run += w; }
    }
    __syncthreads();

    int run = wbase[wid] + (v - s);   // exclusive prefix
    #pragma unroll
    for (int i = 0; i < SCAN_ITEMS; i++) {
        int idx = base + i;
        if (idx < N_NODES) {
            g_off[idx] = run;
            g_pos[idx] = run;
            run += c[i];
        }
    }
}

// ---------------------------------------------------------------------------
// Kernel 4: bin edges into CSR, computing w per edge. 4 edges/thread.
// ---------------------------------------------------------------------------
__global__ __launch_bounds__(256)
void bin_kernel(const void* __restrict__ ei)
{
    int t = blockIdx.x * blockDim.x + threadIdx.x;
    if (t >= E_EDGES / 4) return;
    int4 s4, d4;
    if (g_idx32) {
        s4 = reinterpret_cast<const int4*>(ei)[t];
        d4 = reinterpret_cast<const int4*>(ei)[E_EDGES / 4 + t];
    } else {
        longlong2 p0 = reinterpret_cast<const longlong2*>(ei)[2 * t];
        longlong2 p1 = reinterpret_cast<const longlong2*>(ei)[2 * t + 1];
        longlong2 q0 = reinterpret_cast<const longlong2*>(ei)[E_EDGES / 2 + 2 * t];
        longlong2 q1 = reinterpret_cast<const longlong2*>(ei)[E_EDGES / 2 + 2 * t + 1];
        s4 = make_int4((int)p0.x, (int)p0.y, (int)p1.x, (int)p1.y);
        d4 = make_int4((int)q0.x, (int)q0.y, (int)q1.x, (int)q1.y);
    }
    int ss[4] = {s4.x, s4.y, s4.z, s4.w};
    int dd[4] = {d4.x, d4.y, d4.z, d4.w};
    #pragma unroll
    for (int i = 0; i < 4; i++) {
        float score = g_ssrc[ss[i]] + g_sdst[dd[i]];
        float lr = score > 0.f ? score : SLOPE * score;
        float w = __expf(lr);
        int pos = atomicAdd(&g_pos[ss[i]], 1);
        g_edge[pos] = make_int2(dd[i], __float_as_int(w));
    }
}

// ---------------------------------------------------------------------------
// Kernel 5: aggregate. One warp per node; 16 lanes per edge (float4 each),
// 2 edge-substreams per warp, 8-deep unroll = 16 outstanding loads/warp.
// ---------------------------------------------------------------------------
__global__ __launch_bounds__(256)
void aggregate_kernel(float* __restrict__ out)
{
    const int warp = (blockIdx.x * blockDim.x + threadIdx.x) >> 5;
    const int lane = threadIdx.x & 31;
    if (warp >= N_NODES) return;

    const int sub = lane >> 4;      // which of 2 concurrent edges
    const int sl  = lane & 15;      // float4 slot within a row

    const int beg = g_off[warp];
    const int end = beg + g_cnt[warp];

    unsigned long long axy = 0, azw = 0;   // packed accumulators
    float rsum = 0.f;
    const ulonglong2* gn = reinterpret_cast<const ulonglong2*>(g_new);

    int j = beg + sub;
    // 8 edges per substream iteration -> 16 LDG.128 in flight per warp
    for (; j + 14 < end; j += 16) {
        int2 e0 = g_edge[j + 0];
        int2 e1 = g_edge[j + 2];
        int2 e2 = g_edge[j + 4];
        int2 e3 = g_edge[j + 6];
        int2 e4 = g_edge[j + 8];
        int2 e5 = g_edge[j + 10];
        int2 e6 = g_edge[j + 12];
        int2 e7 = g_edge[j + 14];
        ulonglong2 v0 = gn[(size_t)e0.x * 16 + sl];
        ulonglong2 v1 = gn[(size_t)e1.x * 16 + sl];
        ulonglong2 v2 = gn[(size_t)e2.x * 16 + sl];
        ulonglong2 v3 = gn[(size_t)e3.x * 16 + sl];
        ulonglong2 v4 = gn[(size_t)e4.x * 16 + sl];
        ulonglong2 v5 = gn[(size_t)e5.x * 16 + sl];
        ulonglong2 v6 = gn[(size_t)e6.x * 16 + sl];
        ulonglong2 v7 = gn[(size_t)e7.x * 16 + sl];
        float w0 = __int_as_float(e0.y), w1 = __int_as_float(e1.y);
        float w2 = __int_as_float(e2.y), w3 = __int_as_float(e3.y);
        float w4 = __int_as_float(e4.y), w5 = __int_as_float(e5.y);
        float w6 = __int_as_float(e6.y), w7 = __int_as_float(e7.y);
        unsigned long long wd0 = pack2(w0, w0), wd1 = pack2(w1, w1);
        unsigned long long wd2 = pack2(w2, w2), wd3 = pack2(w3, w3);
        unsigned long long wd4 = pack2(w4, w4), wd5 = pack2(w5, w5);
        unsigned long long wd6 = pack2(w6, w6), wd7 = pack2(w7, w7);
        fma2(axy, wd0, v0.x); fma2(azw, wd0, v0.y);
        fma2(axy, wd1, v1.x); fma2(azw, wd1, v1.y);
        fma2(axy, wd2, v2.x); fma2(azw, wd2, v2.y);
        fma2(axy, wd3, v3.x); fma2(azw, wd3, v3.y);
        fma2(axy, wd4, v4.x); fma2(azw, wd4, v4.y);
        fma2(axy, wd5, v5.x); fma2(azw, wd5, v5.y);
        fma2(axy, wd6, v6.x); fma2(azw, wd6, v6.y);
        fma2(axy, wd7, v7.x); fma2(azw, wd7, v7.y);
        rsum += ((w0 + w1) + (w2 + w3)) + ((w4 + w5) + (w6 + w7));
    }
    for (; j < end; j += 2) {
        int2 e0 = g_edge[j];
        ulonglong2 v0 = gn[(size_t)e0.x * 16 + sl];
        float w0 = __int_as_float(e0.y);
        unsigned long long wd0 = pack2(w0, w0);
        fma2(axy, wd0, v0.x); fma2(azw, wd0, v0.y);
        rsum += w0;
    }

    float2 vxy = unpack2(axy);
    float2 vzw = unpack2(azw);
    float4 acc = make_float4(vxy.x, vxy.y, vzw.x, vzw.y);

    // combine the two edge-substreams (lanes l <-> l+16 hold same columns)
    acc.x += __shfl_xor_sync(0xffffffffu, acc.x, 16);
    acc.y += __shfl_xor_sync(0xffffffffu, acc.y, 16);
    acc.z += __shfl_xor_sync(0xffffffffu, acc.z, 16);
    acc.w += __shfl_xor_sync(0xffffffffu, acc.w, 16);
    rsum  += __shfl_xor_sync(0xffffffffu, rsum, 16);

    if (sub == 0) {
        float inv = 1.0f / (rsum + EPS);
        reinterpret_cast<float4*>(out)[(size_t)warp * 16 + sl] =
            make_float4(acc.x * inv, acc.y * inv, acc.z * inv, acc.w * inv);
    }
}

extern "C" void kernel_launch(void* const* d_in, const int* in_sizes, int n_in,
                              void* d_out, int out_size)
{
    // Size-based dispatch (all element counts distinct) — immune to ordering.
    const float* x = 0; const void* ei = 0; const float* W = 0;
    const float* b = 0; const float* a = 0;
    for (int i = 0; i < n_in; i++) {
        switch (in_sizes[i]) {
            case N_NODES * IN_DIM:       x  = (const float*)d_in[i]; break; // 6.4M
            case 2 * E_EDGES:            ei = d_in[i];               break; // 3.2M
            case OUT_DIM * IN_DIM:       W  = (const float*)d_in[i]; break; // 8192
            case OUT_DIM:                b  = (const float*)d_in[i]; break; // 64
            case 2 * OUT_DIM:            a  = (const float*)d_in[i]; break; // 128
        }
    }
    float* out = (float*)d_out;

    probe_zero_kernel<<<(N_NODES + 255) / 256, 256>>>((const unsigned*)ei);
    gemm_attn_hist_kernel<<<(N_NODES + GEMM_ROWS - 1) / GEMM_ROWS, 128>>>(x, W, b, a, ei);
    scan_part_kernel<<<SCAN_BLOCKS, SCAN_THREADS>>>();
    scan_write_kernel<<<SCAN_BLOCKS, SCAN_THREADS>>>();
    bin_kernel<<<(E_EDGES / 4 + 255) / 256, 256>>>(ei);
    aggregate_kernel<<<(N_NODES * 32 + 255) / 256, 256>>>(out);
}